// round 1
// baseline (speedup 1.0000x reference)
#include <cuda_runtime.h>
#include <math.h>

// Problem constants (fixed shapes from reference)
#define NB 16          // batch
#define NC 64          // channels
#define NHW 65536      // 256*256 pixels per image
#define CHUNKS 64      // HW chunks per image for the reduction
#define PIX_PER_CHUNK (NHW / CHUNKS)   // 1024
#define CONV_NUM 7

// Scratch (allocation-free: __device__ globals)
// Partials stored as float4 per channel-quad: index (b*CHUNKS+chunk)*16 + c4
__device__ float4 g_pmax[NB * CHUNKS * 16];
__device__ float4 g_psum[NB * CHUNKS * 16];
__device__ float4 g_scores4[NB * 16];   // sigmoid scores, (b, c) as float4 quads

// ---------------------------------------------------------------------------
// Kernel 1: per-(image, chunk) max & sum reduction over pixels, per channel.
// Block = 256 threads = 16 channel-quads (c4) x 16 pixel lanes (p0).
// Each pixel row is 64 floats = 16 float4 -> fully coalesced 128B+ accesses.
// ---------------------------------------------------------------------------
__global__ void __launch_bounds__(256) reduce_kernel(const float* __restrict__ feat) {
    const int blk   = blockIdx.x;          // 0 .. NB*CHUNKS-1
    const int b     = blk >> 6;            // / CHUNKS
    const int chunk = blk & 63;            // % CHUNKS

    const float4* __restrict__ base =
        reinterpret_cast<const float4*>(feat)
        + (size_t)b * NHW * 16
        + (size_t)chunk * PIX_PER_CHUNK * 16;

    const int tid = threadIdx.x;
    const int c4  = tid & 15;   // channel quad 0..15
    const int p0  = tid >> 4;   // pixel lane 0..15

    const float NEG_INF = -__int_as_float(0x7f800000);
    float4 mx = make_float4(NEG_INF, NEG_INF, NEG_INF, NEG_INF);
    float4 sm = make_float4(0.f, 0.f, 0.f, 0.f);

    #pragma unroll 4
    for (int p = p0; p < PIX_PER_CHUNK; p += 16) {
        float4 v = base[(size_t)p * 16 + c4];
        mx.x = fmaxf(mx.x, v.x); mx.y = fmaxf(mx.y, v.y);
        mx.z = fmaxf(mx.z, v.z); mx.w = fmaxf(mx.w, v.w);
        sm.x += v.x; sm.y += v.y; sm.z += v.z; sm.w += v.w;
    }

    __shared__ float4 smax[256];
    __shared__ float4 ssum[256];
    smax[tid] = mx;
    ssum[tid] = sm;
    __syncthreads();

    // Tree-reduce across the 16 pixel lanes (stride in units of 16 threads)
    #pragma unroll
    for (int s = 8; s >= 1; s >>= 1) {
        if (p0 < s) {
            int o = tid + s * 16;
            float4 om = smax[o], os = ssum[o];
            float4 m = smax[tid], su = ssum[tid];
            m.x = fmaxf(m.x, om.x); m.y = fmaxf(m.y, om.y);
            m.z = fmaxf(m.z, om.z); m.w = fmaxf(m.w, om.w);
            su.x += os.x; su.y += os.y; su.z += os.z; su.w += os.w;
            smax[tid] = m; ssum[tid] = su;
        }
        __syncthreads();
    }

    if (p0 == 0) {
        g_pmax[(size_t)blk * 16 + c4] = smax[tid];
        g_psum[(size_t)blk * 16 + c4] = ssum[tid];
    }
}

// ---------------------------------------------------------------------------
// Kernel 2: finish reduction + 7 residual PReLU blocks on both branches +
// sigmoid. One block of 1024 threads; thread = (b, c).
// ---------------------------------------------------------------------------
__global__ void __launch_bounds__(1024) mlp_kernel(const float* __restrict__ W1,
                                                   const float* __restrict__ b1,
                                                   const float* __restrict__ a1) {
    const int tid = threadIdx.x;      // 0..1023
    const int b = tid >> 6;           // batch
    const int c = tid & 63;           // channel

    // Reduce chunk partials for this (b, c)
    const float* pmax = reinterpret_cast<const float*>(g_pmax);
    const float* psum = reinterpret_cast<const float*>(g_psum);
    float mx = -__int_as_float(0x7f800000);
    float sm = 0.f;
    #pragma unroll 8
    for (int ch = 0; ch < CHUNKS; ch++) {
        size_t idx = ((size_t)(b * CHUNKS + ch)) * NC + c;
        mx = fmaxf(mx, pmax[idx]);
        sm += psum[idx];
    }
    float avg = sm * (1.0f / (float)NHW);

    __shared__ float xs_max[NB][NC];
    __shared__ float xs_avg[NB][NC];
    xs_max[b][c] = mx;
    xs_avg[b][c] = avg;
    __syncthreads();

    for (int k = 0; k < CONV_NUM; k++) {
        const float* Wk = W1 + (size_t)k * NC * NC;   // row c: Wk[c*NC + j]
        const float bias = b1[k * NC + c];
        const float a = a1[k];
        float accm = bias, acca = bias;
        #pragma unroll
        for (int j = 0; j < NC; j++) {
            float w = Wk[c * NC + j];
            accm = fmaf(w, xs_max[b][j], accm);
            acca = fmaf(w, xs_avg[b][j], acca);
        }
        float nm = (accm >= 0.f ? accm : a * accm) + xs_max[b][c];
        float na = (acca >= 0.f ? acca : a * acca) + xs_avg[b][c];
        __syncthreads();
        xs_max[b][c] = nm;
        xs_avg[b][c] = na;
        __syncthreads();
    }

    float s = xs_max[b][c] + xs_avg[b][c];
    float sig = 1.0f / (1.0f + __expf(-s));
    reinterpret_cast<float*>(g_scores4)[b * NC + c] = sig;
}

// ---------------------------------------------------------------------------
// Kernel 3: out = features * scores[b, c].  One float4 per thread.
// float4 index i: c4 = i & 15, b = i >> 20  (NHW*16 = 2^20 float4 per image)
// ---------------------------------------------------------------------------
__global__ void __launch_bounds__(256) scale_kernel(const float* __restrict__ feat,
                                                    float* __restrict__ out) {
    const size_t i = (size_t)blockIdx.x * blockDim.x + threadIdx.x;  // float4 idx
    const int c4 = (int)(i & 15);
    const int b  = (int)(i >> 20);

    float4 s = g_scores4[b * 16 + c4];
    float4 v = reinterpret_cast<const float4*>(feat)[i];
    v.x *= s.x; v.y *= s.y; v.z *= s.z; v.w *= s.w;
    reinterpret_cast<float4*>(out)[i] = v;
}

// ---------------------------------------------------------------------------
extern "C" void kernel_launch(void* const* d_in, const int* in_sizes, int n_in,
                              void* d_out, int out_size) {
    const float* features = (const float*)d_in[0];  // (16,256,256,64) f32
    const float* W1       = (const float*)d_in[1];  // (7,64,64) f32
    const float* b1       = (const float*)d_in[2];  // (7,64) f32
    const float* a1       = (const float*)d_in[3];  // (7,) f32
    float* out            = (float*)d_out;

    reduce_kernel<<<NB * CHUNKS, 256>>>(features);
    mlp_kernel<<<1, 1024>>>(W1, b1, a1);

    const size_t total4 = (size_t)NB * NHW * 16;   // 16,777,216 float4
    scale_kernel<<<(unsigned)(total4 / 256), 256>>>(features, out);
}

// round 4
// speedup vs baseline: 1.9784x; 1.9784x over previous
#include <cuda_runtime.h>
#include <math.h>

// Problem constants (fixed shapes from reference)
#define NB 16          // batch
#define NC 64          // channels
#define NHW 65536      // 256*256 pixels per image
#define CHUNKS 64      // HW chunks per image for the reduction
#define PIX_PER_CHUNK (NHW / CHUNKS)   // 1024
#define CONV_NUM 7

// Scratch (allocation-free: __device__ globals)
__device__ float4 g_pmax[NB * CHUNKS * 16];
__device__ float4 g_psum[NB * CHUNKS * 16];
__device__ float4 g_scores4[NB * 16];   // sigmoid scores, (b, c) as float4 quads
__device__ unsigned int g_ticket = 0;   // reduce-blocks-done counter (self-resetting)

// ---------------------------------------------------------------------------
// Kernel 1 (fused): per-(image, chunk) max & sum reduction; the LAST block to
// finish also runs the channel MLP (weights staged in padded smem).
// Block = 256 threads = 16 channel-quads (c4) x 16 pixel lanes (p0).
// ---------------------------------------------------------------------------
__global__ void __launch_bounds__(256) reduce_mlp_kernel(const float* __restrict__ feat,
                                                         const float* __restrict__ W1,
                                                         const float* __restrict__ b1,
                                                         const float* __restrict__ a1) {
    const int blk   = blockIdx.x;          // 0 .. NB*CHUNKS-1
    const int b     = blk >> 6;            // / CHUNKS
    const int chunk = blk & 63;            // % CHUNKS

    const float4* __restrict__ base =
        reinterpret_cast<const float4*>(feat)
        + (size_t)b * NHW * 16
        + (size_t)chunk * PIX_PER_CHUNK * 16;

    const int tid = threadIdx.x;
    const int c4  = tid & 15;   // channel quad 0..15
    const int p0  = tid >> 4;   // pixel lane 0..15

    const float NEG_INF = -__int_as_float(0x7f800000);
    float4 mx = make_float4(NEG_INF, NEG_INF, NEG_INF, NEG_INF);
    float4 sm = make_float4(0.f, 0.f, 0.f, 0.f);

    #pragma unroll 4
    for (int p = p0; p < PIX_PER_CHUNK; p += 16) {
        float4 v = base[(size_t)p * 16 + c4];
        mx.x = fmaxf(mx.x, v.x); mx.y = fmaxf(mx.y, v.y);
        mx.z = fmaxf(mx.z, v.z); mx.w = fmaxf(mx.w, v.w);
        sm.x += v.x; sm.y += v.y; sm.z += v.z; sm.w += v.w;
    }

    __shared__ float4 smax[256];
    __shared__ float4 ssum[256];
    smax[tid] = mx;
    ssum[tid] = sm;
    __syncthreads();

    #pragma unroll
    for (int s = 8; s >= 1; s >>= 1) {
        if (p0 < s) {
            int o = tid + s * 16;
            float4 om = smax[o], os = ssum[o];
            float4 m = smax[tid], su = ssum[tid];
            m.x = fmaxf(m.x, om.x); m.y = fmaxf(m.y, om.y);
            m.z = fmaxf(m.z, om.z); m.w = fmaxf(m.w, om.w);
            su.x += os.x; su.y += os.y; su.z += os.z; su.w += os.w;
            smax[tid] = m; ssum[tid] = su;
        }
        __syncthreads();
    }

    if (p0 == 0) {
        g_pmax[(size_t)blk * 16 + c4] = smax[tid];
        g_psum[(size_t)blk * 16 + c4] = ssum[tid];
    }

    // ---- last-block-does-MLP handoff ----
    __threadfence();                       // make partials visible device-wide
    __shared__ unsigned int s_last;
    __syncthreads();
    if (tid == 0)
        s_last = atomicAdd(&g_ticket, 1u); // ticket in [0, grid)
    __syncthreads();
    if (s_last != (unsigned)(NB * CHUNKS - 1))
        return;                            // not the last block

    // Winner: self-reset ticket for next graph replay (race-free: only winner here)
    if (tid == 0)
        g_ticket = 0;

    // ---- channel MLP: 256 threads, each owns 4 (b,c) pairs (stride 256) ----
    __shared__ float xs_max[NB][NC];
    __shared__ float xs_avg[NB][NC];
    __shared__ float sW[NC * 65];          // padded 64x64 weight tile

    const float* pmax = reinterpret_cast<const float*>(g_pmax);
    const float* psum = reinterpret_cast<const float*>(g_psum);

    #pragma unroll
    for (int r = 0; r < 4; r++) {
        int t = tid + r * 256;             // 0..1023 => (b, c)
        int bb = t >> 6, cc = t & 63;
        float m = NEG_INF, su = 0.f;
        #pragma unroll 8
        for (int ch = 0; ch < CHUNKS; ch++) {
            size_t idx = ((size_t)(bb * CHUNKS + ch)) * NC + cc;
            m = fmaxf(m, pmax[idx]);
            su += psum[idx];
        }
        xs_max[bb][cc] = m;
        xs_avg[bb][cc] = su * (1.0f / (float)NHW);
    }
    __syncthreads();

    for (int k = 0; k < CONV_NUM; k++) {
        // Stage Wk (64x64) into padded smem, coalesced: 16 floats per thread.
        const float* Wk = W1 + (size_t)k * NC * NC;
        #pragma unroll
        for (int i = 0; i < 16; i++) {
            int idx = tid + i * 256;       // 0..4095
            int row = idx >> 6, col = idx & 63;
            sW[row * 65 + col] = Wk[idx];
        }
        __syncthreads();

        const float a = a1[k];
        float nm[4], na[4];
        #pragma unroll
        for (int r = 0; r < 4; r++) {
            int t = tid + r * 256;
            int bb = t >> 6, cc = t & 63;
            const float bias = b1[k * NC + cc];
            float accm = bias, acca = bias;
            const float* wrow = &sW[cc * 65];
            #pragma unroll
            for (int j = 0; j < NC; j++) {
                float w = wrow[j];         // bank (cc + j) % 32 -> conflict-free
                accm = fmaf(w, xs_max[bb][j], accm);
                acca = fmaf(w, xs_avg[bb][j], acca);
            }
            nm[r] = (accm >= 0.f ? accm : a * accm) + xs_max[bb][cc];
            na[r] = (acca >= 0.f ? acca : a * acca) + xs_avg[bb][cc];
        }
        __syncthreads();
        #pragma unroll
        for (int r = 0; r < 4; r++) {
            int t = tid + r * 256;
            int bb = t >> 6, cc = t & 63;
            xs_max[bb][cc] = nm[r];
            xs_avg[bb][cc] = na[r];
        }
        __syncthreads();
    }

    float* scores = reinterpret_cast<float*>(g_scores4);
    #pragma unroll
    for (int r = 0; r < 4; r++) {
        int t = tid + r * 256;
        int bb = t >> 6, cc = t & 63;
        float s = xs_max[bb][cc] + xs_avg[bb][cc];
        scores[bb * NC + cc] = 1.0f / (1.0f + __expf(-s));
    }
    __threadfence();                       // scores visible before kernel 2 reads
}

// ---------------------------------------------------------------------------
// Kernel 2: out = features * scores[b, c].
// Block = 256 threads, covers 2048 consecutive float4 of ONE image.
// 8 float4 per thread, loads batched up front (MLP_p1 = 8).
// Stride 256 between iterations keeps (i & 15) constant per thread.
// ---------------------------------------------------------------------------
#define SCALE_V4_PER_BLOCK 2048
__global__ void __launch_bounds__(256) scale_kernel(const float* __restrict__ feat,
                                                    float* __restrict__ out) {
    const size_t base = (size_t)blockIdx.x * SCALE_V4_PER_BLOCK + threadIdx.x;
    const int b = (int)(base >> 20);       // NHW*16 = 2^20 float4 per image

    __shared__ float4 sS[16];
    if (threadIdx.x < 16)
        sS[threadIdx.x] = g_scores4[b * 16 + threadIdx.x];
    __syncthreads();

    const float4 s = sS[threadIdx.x & 15]; // same channel-quad for all 8 iters

    const float4* __restrict__ fin = reinterpret_cast<const float4*>(feat);
    float4* __restrict__ fout = reinterpret_cast<float4*>(out);

    float4 v[8];
    #pragma unroll
    for (int i = 0; i < 8; i++)
        v[i] = fin[base + (size_t)i * 256];

    #pragma unroll
    for (int i = 0; i < 8; i++) {
        v[i].x *= s.x; v[i].y *= s.y; v[i].z *= s.z; v[i].w *= s.w;
        fout[base + (size_t)i * 256] = v[i];
    }
}

// ---------------------------------------------------------------------------
extern "C" void kernel_launch(void* const* d_in, const int* in_sizes, int n_in,
                              void* d_out, int out_size) {
    const float* features = (const float*)d_in[0];  // (16,256,256,64) f32
    const float* W1       = (const float*)d_in[1];  // (7,64,64) f32
    const float* b1       = (const float*)d_in[2];  // (7,64) f32
    const float* a1       = (const float*)d_in[3];  // (7,) f32
    float* out            = (float*)d_out;

    reduce_mlp_kernel<<<NB * CHUNKS, 256>>>(features, W1, b1, a1);

    const size_t total4 = (size_t)NB * NHW * 16;   // 16,777,216 float4
    scale_kernel<<<(unsigned)(total4 / SCALE_V4_PER_BLOCK), 256>>>(features, out);
}

// round 6
// speedup vs baseline: 2.4292x; 1.2279x over previous
#include <cuda_runtime.h>
#include <math.h>

// Problem constants (fixed shapes from reference)
#define NB 16          // batch
#define NC 64          // channels
#define NHW 65536      // 256*256 pixels per image
#define CHUNKS 64      // HW chunks per image for the reduction
#define PIX_PER_CHUNK (NHW / CHUNKS)   // 1024
#define CONV_NUM 7

// Scratch (allocation-free: __device__ globals)
__device__ float4 g_pmax[NB * CHUNKS * 16];
__device__ float4 g_psum[NB * CHUNKS * 16];
__device__ float4 g_scores4[NB * 16];   // sigmoid scores, (b, c) as float4 quads

// ---------------------------------------------------------------------------
// Kernel 1: per-(image, chunk) max & sum reduction over pixels, per channel.
// Block = 256 threads = 16 channel-quads (c4) x 16 pixel lanes (p0).
// Measured R1: 41.7us @ 82.5% DRAM — near streaming ceiling.
// ---------------------------------------------------------------------------
__global__ void __launch_bounds__(256) reduce_kernel(const float* __restrict__ feat) {
    const int blk   = blockIdx.x;          // 0 .. NB*CHUNKS-1
    const int b     = blk >> 6;            // / CHUNKS
    const int chunk = blk & 63;            // % CHUNKS

    const float4* __restrict__ base =
        reinterpret_cast<const float4*>(feat)
        + (size_t)b * NHW * 16
        + (size_t)chunk * PIX_PER_CHUNK * 16;

    const int tid = threadIdx.x;
    const int c4  = tid & 15;   // channel quad 0..15
    const int p0  = tid >> 4;   // pixel lane 0..15

    const float NEG_INF = -__int_as_float(0x7f800000);
    float4 mx = make_float4(NEG_INF, NEG_INF, NEG_INF, NEG_INF);
    float4 sm = make_float4(0.f, 0.f, 0.f, 0.f);

    #pragma unroll 4
    for (int p = p0; p < PIX_PER_CHUNK; p += 16) {
        float4 v = base[(size_t)p * 16 + c4];
        mx.x = fmaxf(mx.x, v.x); mx.y = fmaxf(mx.y, v.y);
        mx.z = fmaxf(mx.z, v.z); mx.w = fmaxf(mx.w, v.w);
        sm.x += v.x; sm.y += v.y; sm.z += v.z; sm.w += v.w;
    }

    __shared__ float4 smax[256];
    __shared__ float4 ssum[256];
    smax[tid] = mx;
    ssum[tid] = sm;
    __syncthreads();

    #pragma unroll
    for (int s = 8; s >= 1; s >>= 1) {
        if (p0 < s) {
            int o = tid + s * 16;
            float4 om = smax[o], os = ssum[o];
            float4 m = smax[tid], su = ssum[tid];
            m.x = fmaxf(m.x, om.x); m.y = fmaxf(m.y, om.y);
            m.z = fmaxf(m.z, om.z); m.w = fmaxf(m.w, om.w);
            su.x += os.x; su.y += os.y; su.z += os.z; su.w += os.w;
            smax[tid] = m; ssum[tid] = su;
        }
        __syncthreads();
    }

    if (p0 == 0) {
        g_pmax[(size_t)blk * 16 + c4] = smax[tid];
        g_psum[(size_t)blk * 16 + c4] = ssum[tid];
    }
}

// ---------------------------------------------------------------------------
// Kernel 2: finish reduction + 7 residual PReLU blocks + sigmoid.
// One block of 1024 threads; thread = (b, c).
// Weight tile staged in smem (stride-65 pad -> conflict-free LDS rows).
// ---------------------------------------------------------------------------
__global__ void __launch_bounds__(1024) mlp_kernel(const float* __restrict__ W1,
                                                   const float* __restrict__ b1,
                                                   const float* __restrict__ a1) {
    const int tid = threadIdx.x;      // 0..1023
    const int b = tid >> 6;           // batch
    const int c = tid & 63;           // channel

    __shared__ float xs_max[NB][NC];
    __shared__ float xs_avg[NB][NC];
    __shared__ float sW[NC * 65];     // padded 64x64 tile

    // Reduce chunk partials for this (b, c) — coalesced (lanes = consecutive c)
    const float* pmax = reinterpret_cast<const float*>(g_pmax);
    const float* psum = reinterpret_cast<const float*>(g_psum);
    float mx = -__int_as_float(0x7f800000);
    float sm = 0.f;
    #pragma unroll 8
    for (int ch = 0; ch < CHUNKS; ch++) {
        size_t idx = ((size_t)(b * CHUNKS + ch)) * NC + c;
        mx = fmaxf(mx, pmax[idx]);
        sm += psum[idx];
    }
    float avg = sm * (1.0f / (float)NHW);

    xs_max[b][c] = mx;
    xs_avg[b][c] = avg;
    __syncthreads();

    for (int k = 0; k < CONV_NUM; k++) {
        // Stage Wk (64x64) into padded smem, coalesced: 4 floats per thread.
        const float* Wk = W1 + (size_t)k * NC * NC;
        #pragma unroll
        for (int i = 0; i < 4; i++) {
            int idx = tid + i * 1024;          // 0..4095
            int row = idx >> 6, col = idx & 63;
            sW[row * 65 + col] = Wk[idx];
        }
        __syncthreads();

        const float bias = b1[k * NC + c];
        const float a = a1[k];
        float accm = bias, acca = bias;
        const float* wrow = &sW[c * 65];
        #pragma unroll
        for (int j = 0; j < NC; j++) {
            float w = wrow[j];                 // bank (c + j) % 32 -> conflict-free
            accm = fmaf(w, xs_max[b][j], accm);
            acca = fmaf(w, xs_avg[b][j], acca);
        }
        float nm = (accm >= 0.f ? accm : a * accm) + xs_max[b][c];
        float na = (acca >= 0.f ? acca : a * acca) + xs_avg[b][c];
        __syncthreads();
        xs_max[b][c] = nm;
        xs_avg[b][c] = na;
        __syncthreads();
    }

    float s = xs_max[b][c] + xs_avg[b][c];
    float sig = 1.0f / (1.0f + __expf(-s));
    reinterpret_cast<float*>(g_scores4)[b * NC + c] = sig;
}

// ---------------------------------------------------------------------------
// Kernel 3: out = features * scores[b, c].
// Block covers 2048 consecutive float4 of ONE image; 8 float4/thread batched.
// blockIdx REVERSED so the first waves read the features that reduce_kernel
// touched last — those are still resident in the 126MB L2.
// ---------------------------------------------------------------------------
#define SCALE_V4_PER_BLOCK 2048
#define SCALE_GRID (NB * NHW * 16 / SCALE_V4_PER_BLOCK)   // 8192
__global__ void __launch_bounds__(256) scale_kernel(const float* __restrict__ feat,
                                                    float* __restrict__ out) {
    const unsigned rb = (unsigned)(SCALE_GRID - 1) - blockIdx.x;   // reversed
    const size_t base = (size_t)rb * SCALE_V4_PER_BLOCK + threadIdx.x;
    const int b = (int)(base >> 20);       // NHW*16 = 2^20 float4 per image

    __shared__ float4 sS[16];
    if (threadIdx.x < 16)
        sS[threadIdx.x] = g_scores4[b * 16 + threadIdx.x];
    __syncthreads();

    const float4 s = sS[threadIdx.x & 15]; // same channel-quad for all 8 iters

    const float4* __restrict__ fin = reinterpret_cast<const float4*>(feat);
    float4* __restrict__ fout = reinterpret_cast<float4*>(out);

    float4 v[8];
    #pragma unroll
    for (int i = 0; i < 8; i++)
        v[i] = fin[base + (size_t)i * 256];

    #pragma unroll
    for (int i = 0; i < 8; i++) {
        v[i].x *= s.x; v[i].y *= s.y; v[i].z *= s.z; v[i].w *= s.w;
        fout[base + (size_t)i * 256] = v[i];
    }
}

// ---------------------------------------------------------------------------
extern "C" void kernel_launch(void* const* d_in, const int* in_sizes, int n_in,
                              void* d_out, int out_size) {
    const float* features = (const float*)d_in[0];  // (16,256,256,64) f32
    const float* W1       = (const float*)d_in[1];  // (7,64,64) f32
    const float* b1       = (const float*)d_in[2];  // (7,64) f32
    const float* a1       = (const float*)d_in[3];  // (7,) f32
    float* out            = (float*)d_out;

    reduce_kernel<<<NB * CHUNKS, 256>>>(features);
    mlp_kernel<<<1, 1024>>>(W1, b1, a1);
    scale_kernel<<<SCALE_GRID, 256>>>(features, out);
}

// round 8
// speedup vs baseline: 2.6409x; 1.0872x over previous
#include <cuda_runtime.h>
#include <math.h>

// Problem constants (fixed shapes from reference)
#define NB 16          // batch
#define NC 64          // channels
#define NHW 65536      // 256*256 pixels per image
#define CHUNKS 64      // HW chunks per image for the reduction
#define PIX_PER_CHUNK (NHW / CHUNKS)   // 1024
#define CONV_NUM 7

// Scratch (allocation-free: __device__ globals)
__device__ float4 g_pmax[NB * CHUNKS * 16];
__device__ float4 g_psum[NB * CHUNKS * 16];
__device__ float4 g_scores4[NB * 16];   // sigmoid scores, (b, c) as float4 quads

// ---------------------------------------------------------------------------
// Kernel 1: per-(image, chunk) max & sum reduction over pixels, per channel.
// Block = 256 threads = 16 channel-quads (c4) x 16 pixel lanes (p0).
// Measured: 41.9us @ 82.3% DRAM — at the LTS ceiling. Do not touch.
// ---------------------------------------------------------------------------
__global__ void __launch_bounds__(256) reduce_kernel(const float* __restrict__ feat) {
    const int blk   = blockIdx.x;          // 0 .. NB*CHUNKS-1
    const int b     = blk >> 6;            // / CHUNKS
    const int chunk = blk & 63;            // % CHUNKS

    const float4* __restrict__ base =
        reinterpret_cast<const float4*>(feat)
        + (size_t)b * NHW * 16
        + (size_t)chunk * PIX_PER_CHUNK * 16;

    const int tid = threadIdx.x;
    const int c4  = tid & 15;   // channel quad 0..15
    const int p0  = tid >> 4;   // pixel lane 0..15

    const float NEG_INF = -__int_as_float(0x7f800000);
    float4 mx = make_float4(NEG_INF, NEG_INF, NEG_INF, NEG_INF);
    float4 sm = make_float4(0.f, 0.f, 0.f, 0.f);

    #pragma unroll 4
    for (int p = p0; p < PIX_PER_CHUNK; p += 16) {
        float4 v = base[(size_t)p * 16 + c4];
        mx.x = fmaxf(mx.x, v.x); mx.y = fmaxf(mx.y, v.y);
        mx.z = fmaxf(mx.z, v.z); mx.w = fmaxf(mx.w, v.w);
        sm.x += v.x; sm.y += v.y; sm.z += v.z; sm.w += v.w;
    }

    __shared__ float4 smax[256];
    __shared__ float4 ssum[256];
    smax[tid] = mx;
    ssum[tid] = sm;
    __syncthreads();

    #pragma unroll
    for (int s = 8; s >= 1; s >>= 1) {
        if (p0 < s) {
            int o = tid + s * 16;
            float4 om = smax[o], os = ssum[o];
            float4 m = smax[tid], su = ssum[tid];
            m.x = fmaxf(m.x, om.x); m.y = fmaxf(m.y, om.y);
            m.z = fmaxf(m.z, om.z); m.w = fmaxf(m.w, om.w);
            su.x += os.x; su.y += os.y; su.z += os.z; su.w += os.w;
            smax[tid] = m; ssum[tid] = su;
        }
        __syncthreads();
    }

    if (p0 == 0) {
        g_pmax[(size_t)blk * 16 + c4] = smax[tid];
        g_psum[(size_t)blk * 16 + c4] = ssum[tid];
    }
}

// ---------------------------------------------------------------------------
// Kernel 2: finish reduction + 7 residual PReLU blocks + sigmoid.
// 16 blocks (one per image) x 64 threads (one per channel).
// Weights staged per-layer into padded float4 smem (stride 17 float4 = 68
// floats -> LDS.128 banks (4c+4i)%32 conflict-free). xs vectors read as
// same-address float4 broadcasts (free).
// ---------------------------------------------------------------------------
__global__ void __launch_bounds__(64) mlp_kernel(const float* __restrict__ W1,
                                                 const float* __restrict__ b1,
                                                 const float* __restrict__ a1) {
    const int b = blockIdx.x;     // image
    const int c = threadIdx.x;    // channel 0..63

    __shared__ float xs_max[NC];
    __shared__ float xs_avg[NC];
    __shared__ float4 sW4[NC * 17];   // padded 64x64 tile, float4 granularity

    // Finish the chunk-partial reduction for (b, c): coalesced 128B warp loads
    const float* pmax = reinterpret_cast<const float*>(g_pmax);
    const float* psum = reinterpret_cast<const float*>(g_psum);
    float mx = -__int_as_float(0x7f800000);
    float sm = 0.f;
    #pragma unroll 8
    for (int ch = 0; ch < CHUNKS; ch++) {
        int idx = (b * CHUNKS + ch) * NC + c;
        mx = fmaxf(mx, pmax[idx]);
        sm += psum[idx];
    }
    xs_max[c] = mx;
    xs_avg[c] = sm * (1.0f / (float)NHW);
    __syncthreads();

    const float4* xsm4 = reinterpret_cast<const float4*>(xs_max);
    const float4* xsa4 = reinterpret_cast<const float4*>(xs_avg);

    for (int k = 0; k < CONV_NUM; k++) {
        // Stage Wk (1024 float4) coalesced: 16 float4 per thread.
        const float4* Wk4 = reinterpret_cast<const float4*>(W1 + (size_t)k * NC * NC);
        #pragma unroll
        for (int i = 0; i < 16; i++) {
            int idx4 = c + i * 64;             // 0..1023
            int row = idx4 >> 4, col4 = idx4 & 15;
            sW4[row * 17 + col4] = Wk4[idx4];
        }
        __syncthreads();

        const float bias = b1[k * NC + c];
        const float a = a1[k];
        float accm = bias, acca = bias;
        const float4* wrow = &sW4[c * 17];
        #pragma unroll
        for (int i = 0; i < 16; i++) {
            float4 w = wrow[i];                // conflict-free LDS.128
            float4 xm = xsm4[i];               // broadcast
            float4 xa = xsa4[i];               // broadcast
            accm = fmaf(w.x, xm.x, accm); acca = fmaf(w.x, xa.x, acca);
            accm = fmaf(w.y, xm.y, accm); acca = fmaf(w.y, xa.y, acca);
            accm = fmaf(w.z, xm.z, accm); acca = fmaf(w.z, xa.z, acca);
            accm = fmaf(w.w, xm.w, accm); acca = fmaf(w.w, xa.w, acca);
        }
        float nm = (accm >= 0.f ? accm : a * accm) + xs_max[c];
        float na = (acca >= 0.f ? acca : a * acca) + xs_avg[c];
        __syncthreads();
        xs_max[c] = nm;
        xs_avg[c] = na;
        __syncthreads();
    }

    float s = xs_max[c] + xs_avg[c];
    reinterpret_cast<float*>(g_scores4)[b * NC + c] = 1.0f / (1.0f + __expf(-s));
}

// ---------------------------------------------------------------------------
// Kernel 3: out = features * scores[b, c].
// Block covers 2048 consecutive float4 of ONE image; 8 float4/thread batched.
// blockIdx REVERSED so the first waves read the features that reduce_kernel
// touched last — those are still resident in the 126MB L2.
// ---------------------------------------------------------------------------
#define SCALE_V4_PER_BLOCK 2048
#define SCALE_GRID (NB * NHW * 16 / SCALE_V4_PER_BLOCK)   // 8192
__global__ void __launch_bounds__(256) scale_kernel(const float* __restrict__ feat,
                                                    float* __restrict__ out) {
    const unsigned rb = (unsigned)(SCALE_GRID - 1) - blockIdx.x;   // reversed
    const size_t base = (size_t)rb * SCALE_V4_PER_BLOCK + threadIdx.x;
    const int b = (int)(base >> 20);       // NHW*16 = 2^20 float4 per image

    __shared__ float4 sS[16];
    if (threadIdx.x < 16)
        sS[threadIdx.x] = g_scores4[b * 16 + threadIdx.x];
    __syncthreads();

    const float4 s = sS[threadIdx.x & 15]; // same channel-quad for all 8 iters

    const float4* __restrict__ fin = reinterpret_cast<const float4*>(feat);
    float4* __restrict__ fout = reinterpret_cast<float4*>(out);

    float4 v[8];
    #pragma unroll
    for (int i = 0; i < 8; i++)
        v[i] = fin[base + (size_t)i * 256];

    #pragma unroll
    for (int i = 0; i < 8; i++) {
        v[i].x *= s.x; v[i].y *= s.y; v[i].z *= s.z; v[i].w *= s.w;
        fout[base + (size_t)i * 256] = v[i];
    }
}

// ---------------------------------------------------------------------------
extern "C" void kernel_launch(void* const* d_in, const int* in_sizes, int n_in,
                              void* d_out, int out_size) {
    const float* features = (const float*)d_in[0];  // (16,256,256,64) f32
    const float* W1       = (const float*)d_in[1];  // (7,64,64) f32
    const float* b1       = (const float*)d_in[2];  // (7,64) f32
    const float* a1       = (const float*)d_in[3];  // (7,) f32
    float* out            = (float*)d_out;

    reduce_kernel<<<NB * CHUNKS, 256>>>(features);
    mlp_kernel<<<NB, 64>>>(W1, b1, a1);
    scale_kernel<<<SCALE_GRID, 256>>>(features, out);
}